// round 11
// baseline (speedup 1.0000x reference)
#include <cuda_runtime.h>
#include <cuda_fp16.h>

// Problem constants (fixed by the reference: B=4, N=1024, FMAP=64, HID=32)
#define BB 4
#define NN 1024
#define FM 64
#define HID 32
#define ROWS (BB * NN)        // 4096
#define I_CHUNK 32
#define JT 128
#define NBLOCKS 1024          // (8, 32, 4) — single wave, all co-resident
#define PREP_BLOCKS 256       // only these do phase A (16 rows each)

// Projections, packed as half (32 per row = 16 half2). Written in phase A.
__device__ __align__(16) __half2 g_A[ROWS * 16];  // A' = X@W1a + b1
__device__ __align__(16) __half2 g_C[ROWS * 16];  // C  = X@W1b

// Grid barrier state (replay-safe: count self-resets, gen is monotone).
__device__ unsigned g_count;   // zero-init at module load
__device__ unsigned g_gen;

__device__ __forceinline__ __half2 tanh2_approx(__half2 x) {
    unsigned xi = *reinterpret_cast<unsigned*>(&x);
    unsigned ri;
    asm("tanh.approx.f16x2 %0, %1;" : "=r"(ri) : "r"(xi));
    return *reinterpret_cast<__half2*>(&ri);
}

__device__ __forceinline__ float tanhf_approx(float x) {
    float r;
    asm("tanh.approx.f32 %0, %1;" : "=f"(r) : "f"(x));
    return r;
}

__global__ __launch_bounds__(JT, 8) void fused_kernel(
    const float* __restrict__ X,    // [ROWS, 64]
    const float* __restrict__ W1,   // [128, 32]
    const float* __restrict__ b1,   // [32]
    const float* __restrict__ W2,   // [32]
    const float* __restrict__ b2,   // [1]
    float* __restrict__ out)        // [B, N, N]
{
    // Phase A uses sW1 (16 KB); phase B reuses the same space as sC (2 KB).
    __shared__ __align__(16) float sW1[2 * FM * HID];
    __half2* sC = reinterpret_cast<__half2*>(sW1);

    const int t    = threadIdx.x;
    const int warp = t >> 5;
    const int lane = t & 31;
    const int bid  = blockIdx.x + 8 * blockIdx.y + 256 * blockIdx.z;  // 0..1023

    // ============ Phase A: prep — only PREP_BLOCKS blocks work ==========
    if (bid < PREP_BLOCKS) {
        // Stage W1 (16 KB): 1024 float4 / 128 threads = 8 each.
        const float4* w4 = reinterpret_cast<const float4*>(W1);
        float4* s4 = reinterpret_cast<float4*>(sW1);
        #pragma unroll
        for (int q = 0; q < 8; q++) s4[t + 128 * q] = w4[t + 128 * q];

        const float bias = b1[lane];
        __syncthreads();   // uniform within prep blocks

        const int row0 = bid * 16 + warp * 4;   // 4 rows per warp
        for (int r = 0; r < 4; r++) {
            const int row = row0 + r;
            // X row: 2 regs per lane, broadcast via shfl.
            float x0 = X[row * FM + lane];
            float x1 = X[row * FM + lane + 32];
            float a  = bias;   // fold b1 into A'
            float c  = 0.0f;

            #pragma unroll
            for (int k = 0; k < 32; k++) {
                float xk = __shfl_sync(0xffffffffu, x0, k);
                a = fmaf(xk, sW1[k * HID + lane], a);
                c = fmaf(xk, sW1[(k + FM) * HID + lane], c);
            }
            #pragma unroll
            for (int k = 0; k < 32; k++) {
                float xk = __shfl_sync(0xffffffffu, x1, k);
                a = fmaf(xk, sW1[(k + 32) * HID + lane], a);
                c = fmaf(xk, sW1[(k + 32 + FM) * HID + lane], c);
            }
            reinterpret_cast<__half*>(g_A)[row * HID + lane] = __float2half_rn(a);
            reinterpret_cast<__half*>(g_C)[row * HID + lane] = __float2half_rn(c);
        }
    }

    // All blocks: pack W2/2 + b2/2 (cheap; overlaps stragglers).
    __half2 w2h[16];
    #pragma unroll
    for (int k = 0; k < 16; k++)
        w2h[k] = __floats2half2_rn(0.5f * W2[2 * k], 0.5f * W2[2 * k + 1]);
    const float bias2 = 0.5f * b2[0];
    const __half2 binit = __halves2half2(__float2half_rn(bias2),
                                         __ushort_as_half((unsigned short)0));
    const __half2 hzero = __float2half2_rn(0.0f);

    // ============ Grid barrier (all 1024 blocks resident, 1 wave) =======
    __syncthreads();   // prep STGs issued (no-op ordering for idle blocks)
    if (t == 0) {
        unsigned my_gen = *(volatile unsigned*)&g_gen;  // read BEFORE arriving
        __threadfence();                                 // release g_A/g_C writes
        unsigned old = atomicAdd(&g_count, 1);
        if (old == NBLOCKS - 1) {
            g_count = 0;                                 // reset for next replay
            __threadfence();
            atomicAdd(&g_gen, 1);                        // release everyone
        } else {
            unsigned g;
            do {
                __nanosleep(64);
                asm volatile("ld.acquire.gpu.u32 %0, [%1];"
                             : "=r"(g) : "l"(&g_gen) : "memory");
            } while (g == my_gen);
        }
    }
    __syncthreads();

    // ============ Phase B: pairwise tanh + dot + sigmoid ================
    const int b  = blockIdx.z;
    const int j  = blockIdx.x * JT + t;
    const int i0 = blockIdx.y * I_CHUNK;

    // C tile (I_CHUNK rows x 16 half2 = 2 KB): 128 float4, one per thread.
    reinterpret_cast<float4*>(sC)[t] =
        __ldcg(reinterpret_cast<const float4*>(g_C + ((size_t)b * NN + i0) * 16) + t);

    // Per-thread A' row (register-resident).
    float4 av[4];
    const float4* gA = reinterpret_cast<const float4*>(g_A + ((size_t)b * NN + j) * 16);
    #pragma unroll
    for (int q = 0; q < 4; q++) av[q] = __ldcg(gA + q);
    const __half2* Aj = reinterpret_cast<const __half2*>(av);

    __syncthreads();

    float* outp = out + (size_t)b * NN * NN + (size_t)i0 * NN + j;

    #pragma unroll 4
    for (int ii = 0; ii < I_CHUNK; ii += 2) {
        const float4* crow0 = reinterpret_cast<const float4*>(sC + ii * 16);
        const float4* crow1 = reinterpret_cast<const float4*>(sC + (ii + 1) * 16);

        // Two independent accumulation chains (i and i+1).
        __half2 a0 = binit, a1 = hzero, a2 = hzero, a3 = hzero;   // i
        __half2 b0 = binit, b1v = hzero, b2v = hzero, b3 = hzero; // i+1

        #pragma unroll
        for (int q = 0; q < 4; q++) {
            float4 cv0 = crow0[q];                      // broadcast LDS.128
            float4 cv1 = crow1[q];
            const __half2* c0 = reinterpret_cast<const __half2*>(&cv0);
            const __half2* c1 = reinterpret_cast<const __half2*>(&cv1);

            __half2 t00 = tanh2_approx(__hadd2(Aj[4 * q + 0], c0[0]));
            __half2 t10 = tanh2_approx(__hadd2(Aj[4 * q + 0], c1[0]));
            __half2 t01 = tanh2_approx(__hadd2(Aj[4 * q + 1], c0[1]));
            __half2 t11 = tanh2_approx(__hadd2(Aj[4 * q + 1], c1[1]));
            __half2 t02 = tanh2_approx(__hadd2(Aj[4 * q + 2], c0[2]));
            __half2 t12 = tanh2_approx(__hadd2(Aj[4 * q + 2], c1[2]));
            __half2 t03 = tanh2_approx(__hadd2(Aj[4 * q + 3], c0[3]));
            __half2 t13 = tanh2_approx(__hadd2(Aj[4 * q + 3], c1[3]));

            a0  = __hfma2(t00, w2h[4 * q + 0], a0);
            b0  = __hfma2(t10, w2h[4 * q + 0], b0);
            a1  = __hfma2(t01, w2h[4 * q + 1], a1);
            b1v = __hfma2(t11, w2h[4 * q + 1], b1v);
            a2  = __hfma2(t02, w2h[4 * q + 2], a2);
            b2v = __hfma2(t12, w2h[4 * q + 2], b2v);
            a3  = __hfma2(t03, w2h[4 * q + 3], a3);
            b3  = __hfma2(t13, w2h[4 * q + 3], b3);
        }

        // Lean epilogue per i: 3 HADD2 + 1 HADD + 1 cvt + MUFU + FFMA + STG.
        __half2 sa = __hadd2(__hadd2(a0, a1), __hadd2(a2, a3));
        __half2 sb = __hadd2(__hadd2(b0, b1v), __hadd2(b2v, b3));
        float hla = __half2float(__hadd(__low2half(sa), __high2half(sa)));
        float hlb = __half2float(__hadd(__low2half(sb), __high2half(sb)));

        outp[(size_t)ii * NN]       = fmaf(0.5f, tanhf_approx(hla), 0.5f);
        outp[(size_t)(ii + 1) * NN] = fmaf(0.5f, tanhf_approx(hlb), 0.5f);
    }
}

// ---------------------------------------------------------------------------
// Launch: ONE graph-capturable kernel, no allocations, no syncs.
// Inputs (metadata order): X, W1, b1, W2, b2. Output: float32 [4,1024,1024].
// ---------------------------------------------------------------------------
extern "C" void kernel_launch(void* const* d_in, const int* in_sizes, int n_in,
                              void* d_out, int out_size)
{
    const float* X  = (const float*)d_in[0];
    const float* W1 = (const float*)d_in[1];
    const float* b1 = (const float*)d_in[2];
    const float* W2 = (const float*)d_in[3];
    const float* b2 = (const float*)d_in[4];
    float* out = (float*)d_out;

    dim3 grid(NN / JT, NN / I_CHUNK, BB);   // (8, 32, 4) = 1024 blocks, 1 wave
    fused_kernel<<<grid, JT>>>(X, W1, b1, W2, b2, out);
}

// round 12
// speedup vs baseline: 1.0582x; 1.0582x over previous
#include <cuda_runtime.h>
#include <cuda_fp16.h>

// Problem constants (fixed by the reference: B=4, N=1024, FMAP=64, HID=32)
#define BB 4
#define NN 1024
#define FM 64
#define HID 32
#define ROWS (BB * NN)        // 4096
#define I_CHUNK 32
#define JT 128
#define NBLOCKS 1024          // (8, 32, 4) — single wave, all co-resident

// Projections, packed as half (32 per row = 16 half2). Written in phase A.
__device__ __align__(16) __half2 g_A[ROWS * 16];  // A' = X@W1a + b1
__device__ __align__(16) __half2 g_C[ROWS * 16];  // C  = X@W1b

// Grid barrier state (replay-safe: count self-resets, gen is monotone).
__device__ unsigned g_count;   // zero-init at module load
__device__ unsigned g_gen;

__device__ __forceinline__ __half2 tanh2_approx(__half2 x) {
    unsigned xi = *reinterpret_cast<unsigned*>(&x);
    unsigned ri;
    asm("tanh.approx.f16x2 %0, %1;" : "=r"(ri) : "r"(xi));
    return *reinterpret_cast<__half2*>(&ri);
}

__device__ __forceinline__ float tanhf_approx(float x) {
    float r;
    asm("tanh.approx.f32 %0, %1;" : "=f"(r) : "f"(x));
    return r;
}

__global__ __launch_bounds__(JT, 8) void fused_kernel(
    const float* __restrict__ X,    // [ROWS, 64]
    const float* __restrict__ W1,   // [128, 32]
    const float* __restrict__ b1,   // [32]
    const float* __restrict__ W2,   // [32]
    const float* __restrict__ b2,   // [1]
    float* __restrict__ out)        // [B, N, N]
{
    // Phase A: sW1 (16 KB) + sX (1 KB). Phase B reuses the space as sC (2 KB).
    __shared__ __align__(16) float sW1[2 * FM * HID];
    __shared__ __align__(16) float sX[4][FM];
    __half2* sC = reinterpret_cast<__half2*>(sW1);

    const int t    = threadIdx.x;
    const int warp = t >> 5;
    const int lane = t & 31;
    const int bid  = blockIdx.x + 8 * blockIdx.y + 256 * blockIdx.z;  // 0..1023

    // ============ Phase A: prep — 4 rows per block, 1 row per warp ======
    {
        // Stage W1 (16 KB): 1024 float4 / 128 threads = 8 each, coalesced.
        const float4* w4 = reinterpret_cast<const float4*>(W1);
        float4* s4 = reinterpret_cast<float4*>(sW1);
        #pragma unroll
        for (int q = 0; q < 8; q++) s4[t + 128 * q] = w4[t + 128 * q];
    }

    const int row = 4 * bid + warp;   // 0..4095; warp owns one row
    // Stage this warp's X row (64 floats): 2 per lane, coalesced.
    sX[warp][lane]      = X[row * FM + lane];
    sX[warp][lane + 32] = X[row * FM + lane + 32];
    const float bias = b1[lane];
    __syncthreads();

    {
        float a = bias;   // fold b1 into A'
        float c = 0.0f;
        #pragma unroll
        for (int k = 0; k < FM; k++) {
            float xk = sX[warp][k];                  // LDS broadcast — pipelined
            a = fmaf(xk, sW1[k * HID + lane], a);
            c = fmaf(xk, sW1[(k + FM) * HID + lane], c);
        }
        reinterpret_cast<__half*>(g_A)[row * HID + lane] = __float2half_rn(a);
        reinterpret_cast<__half*>(g_C)[row * HID + lane] = __float2half_rn(c);
    }

    // All blocks: pack W2/2 + b2/2 (cheap; overlaps stragglers).
    __half2 w2h[16];
    #pragma unroll
    for (int k = 0; k < 16; k++)
        w2h[k] = __floats2half2_rn(0.5f * W2[2 * k], 0.5f * W2[2 * k + 1]);
    const float bias2 = 0.5f * b2[0];
    const __half2 binit = __halves2half2(__float2half_rn(bias2),
                                         __ushort_as_half((unsigned short)0));
    const __half2 hzero = __float2half2_rn(0.0f);

    // ============ Grid barrier (all 1024 blocks resident, 1 wave) =======
    __syncthreads();   // all prep STGs in this block issued; sW1 reads done
    if (t == 0) {
        unsigned my_gen = *(volatile unsigned*)&g_gen;  // read BEFORE arriving
        __threadfence();                                 // release g_A/g_C writes
        unsigned old = atomicAdd(&g_count, 1);
        if (old == NBLOCKS - 1) {
            g_count = 0;                                 // reset for next replay
            __threadfence();
            atomicAdd(&g_gen, 1);                        // release everyone
        } else {
            unsigned g;
            do {
                __nanosleep(32);
                asm volatile("ld.acquire.gpu.u32 %0, [%1];"
                             : "=r"(g) : "l"(&g_gen) : "memory");
            } while (g == my_gen);
        }
    }
    __syncthreads();

    // ============ Phase B: pairwise tanh + dot + sigmoid ================
    const int b  = blockIdx.z;
    const int j  = blockIdx.x * JT + t;
    const int i0 = blockIdx.y * I_CHUNK;

    // C tile (I_CHUNK rows x 16 half2 = 2 KB): 128 float4, one per thread.
    reinterpret_cast<float4*>(sC)[t] =
        __ldcg(reinterpret_cast<const float4*>(g_C + ((size_t)b * NN + i0) * 16) + t);

    // Per-thread A' row (register-resident).
    float4 av[4];
    const float4* gA = reinterpret_cast<const float4*>(g_A + ((size_t)b * NN + j) * 16);
    #pragma unroll
    for (int q = 0; q < 4; q++) av[q] = __ldcg(gA + q);
    const __half2* Aj = reinterpret_cast<const __half2*>(av);

    __syncthreads();

    float* outp = out + (size_t)b * NN * NN + (size_t)i0 * NN + j;

    #pragma unroll 4
    for (int ii = 0; ii < I_CHUNK; ii += 2) {
        const float4* crow0 = reinterpret_cast<const float4*>(sC + ii * 16);
        const float4* crow1 = reinterpret_cast<const float4*>(sC + (ii + 1) * 16);

        // Two independent accumulation chains (i and i+1).
        __half2 a0 = binit, a1 = hzero, a2 = hzero, a3 = hzero;   // i
        __half2 b0 = binit, b1v = hzero, b2v = hzero, b3 = hzero; // i+1

        #pragma unroll
        for (int q = 0; q < 4; q++) {
            float4 cv0 = crow0[q];                      // broadcast LDS.128
            float4 cv1 = crow1[q];
            const __half2* c0 = reinterpret_cast<const __half2*>(&cv0);
            const __half2* c1 = reinterpret_cast<const __half2*>(&cv1);

            __half2 t00 = tanh2_approx(__hadd2(Aj[4 * q + 0], c0[0]));
            __half2 t10 = tanh2_approx(__hadd2(Aj[4 * q + 0], c1[0]));
            __half2 t01 = tanh2_approx(__hadd2(Aj[4 * q + 1], c0[1]));
            __half2 t11 = tanh2_approx(__hadd2(Aj[4 * q + 1], c1[1]));
            __half2 t02 = tanh2_approx(__hadd2(Aj[4 * q + 2], c0[2]));
            __half2 t12 = tanh2_approx(__hadd2(Aj[4 * q + 2], c1[2]));
            __half2 t03 = tanh2_approx(__hadd2(Aj[4 * q + 3], c0[3]));
            __half2 t13 = tanh2_approx(__hadd2(Aj[4 * q + 3], c1[3]));

            a0  = __hfma2(t00, w2h[4 * q + 0], a0);
            b0  = __hfma2(t10, w2h[4 * q + 0], b0);
            a1  = __hfma2(t01, w2h[4 * q + 1], a1);
            b1v = __hfma2(t11, w2h[4 * q + 1], b1v);
            a2  = __hfma2(t02, w2h[4 * q + 2], a2);
            b2v = __hfma2(t12, w2h[4 * q + 2], b2v);
            a3  = __hfma2(t03, w2h[4 * q + 3], a3);
            b3  = __hfma2(t13, w2h[4 * q + 3], b3);
        }

        // Lean epilogue per i: 3 HADD2 + 1 HADD + 1 cvt + MUFU + FFMA + STG.
        __half2 sa = __hadd2(__hadd2(a0, a1), __hadd2(a2, a3));
        __half2 sb = __hadd2(__hadd2(b0, b1v), __hadd2(b2v, b3));
        float hla = __half2float(__hadd(__low2half(sa), __high2half(sa)));
        float hlb = __half2float(__hadd(__low2half(sb), __high2half(sb)));

        outp[(size_t)ii * NN]       = fmaf(0.5f, tanhf_approx(hla), 0.5f);
        outp[(size_t)(ii + 1) * NN] = fmaf(0.5f, tanhf_approx(hlb), 0.5f);
    }
}

// ---------------------------------------------------------------------------
// Launch: ONE graph-capturable kernel, no allocations, no syncs.
// Inputs (metadata order): X, W1, b1, W2, b2. Output: float32 [4,1024,1024].
// ---------------------------------------------------------------------------
extern "C" void kernel_launch(void* const* d_in, const int* in_sizes, int n_in,
                              void* d_out, int out_size)
{
    const float* X  = (const float*)d_in[0];
    const float* W1 = (const float*)d_in[1];
    const float* b1 = (const float*)d_in[2];
    const float* W2 = (const float*)d_in[3];
    const float* b2 = (const float*)d_in[4];
    float* out = (float*)d_out;

    dim3 grid(NN / JT, NN / I_CHUNK, BB);   // (8, 32, 4) = 1024 blocks, 1 wave
    fused_kernel<<<grid, JT>>>(X, W1, b1, W2, b2, out);
}

// round 13
// speedup vs baseline: 1.0802x; 1.0208x over previous
#include <cuda_runtime.h>
#include <cuda_fp16.h>

// Problem constants (fixed by the reference: B=4, N=1024, FMAP=64, HID=32)
#define BB 4
#define NN 1024
#define FM 64
#define HID 32
#define ROWS (BB * NN)        // 4096
#define I_CHUNK 32
#define JT 128
#define NBLOCKS 1024          // (8, 32, 4) — single wave, all co-resident

// Projections, packed as half (32 per row = 16 half2). Written in phase A.
__device__ __align__(16) __half2 g_A[ROWS * 16];  // A' = X@W1a + b1
__device__ __align__(16) __half2 g_C[ROWS * 16];  // C  = X@W1b

// Grid barrier state (replay-safe: count self-resets, gen is monotone).
__device__ unsigned g_count;   // zero-init at module load
__device__ unsigned g_gen;

__device__ __forceinline__ __half2 tanh2_approx(__half2 x) {
    unsigned xi = *reinterpret_cast<unsigned*>(&x);
    unsigned ri;
    asm("tanh.approx.f16x2 %0, %1;" : "=r"(ri) : "r"(xi));
    return *reinterpret_cast<__half2*>(&ri);
}

__device__ __forceinline__ float tanhf_approx(float x) {
    float r;
    asm("tanh.approx.f32 %0, %1;" : "=f"(r) : "f"(x));
    return r;
}

__global__ __launch_bounds__(JT, 8) void fused_kernel(
    const float* __restrict__ X,    // [ROWS, 64]
    const float* __restrict__ W1,   // [128, 32]
    const float* __restrict__ b1,   // [32]
    const float* __restrict__ W2,   // [32]
    const float* __restrict__ b2,   // [1]
    float* __restrict__ out)        // [B, N, N]
{
    // Phase A: sWa/sWc = W1 half2-packed by k-pairs (4 KB each), sX2 (1 KB).
    // Phase B reuses sWa's first 2 KB as the C tile.
    __shared__ __align__(16) __half2 sWa[32 * 32];   // [kp][h], a-half of W1
    __shared__ __align__(16) __half2 sWc[32 * 32];   // [kp][h], c-half of W1
    __shared__ __align__(16) float2  sX2[4][32];
    __half2* sC = sWa;

    const int t    = threadIdx.x;
    const int warp = t >> 5;
    const int lane = t & 31;
    const int bid  = blockIdx.x + 8 * blockIdx.y + 256 * blockIdx.z;  // 0..1023

    // ============ Phase A: prep — 4 rows per block, 1 row per warp ======
    // Stage W1 packed: entry (kp,h) = half2(W1[2kp][h], W1[2kp+1][h]).
    #pragma unroll
    for (int q = 0; q < 8; q++) {
        int idx = t + 128 * q;          // 0..1023
        int kp = idx >> 5, h = idx & 31;
        float w0 = W1[kp * 64 + h];             // W1[2kp][h]   (coalesced)
        float w1 = W1[kp * 64 + 32 + h];        // W1[2kp+1][h]
        sWa[idx] = __floats2half2_rn(w0, w1);
        float v0 = W1[2048 + kp * 64 + h];      // W1b rows
        float v1 = W1[2048 + kp * 64 + 32 + h];
        sWc[idx] = __floats2half2_rn(v0, v1);
    }

    const int row = 4 * bid + warp;   // 0..4095; warp owns one row
    // Stage this warp's X row as 32 float2 (one per lane, coalesced).
    sX2[warp][lane] = reinterpret_cast<const float2*>(X)[row * 32 + lane];
    const float bias = b1[lane];
    __syncthreads();

    {
        float a = bias;   // fold b1 into A'
        float c = 0.0f;
        #pragma unroll
        for (int kp = 0; kp < 32; kp++) {
            float2 xk = sX2[warp][kp];                       // LDS.64 broadcast
            float2 fa = __half22float2(sWa[kp * 32 + lane]); // 1 LDS.32, 2 cvt
            float2 fc = __half22float2(sWc[kp * 32 + lane]);
            a = fmaf(xk.x, fa.x, a); a = fmaf(xk.y, fa.y, a);
            c = fmaf(xk.x, fc.x, c); c = fmaf(xk.y, fc.y, c);
        }
        reinterpret_cast<__half*>(g_A)[row * HID + lane] = __float2half_rn(a);
        reinterpret_cast<__half*>(g_C)[row * HID + lane] = __float2half_rn(c);
    }

    // All blocks: pack W2/2 + b2/2 (cheap; overlaps stragglers).
    __half2 w2h[16];
    #pragma unroll
    for (int k = 0; k < 16; k++)
        w2h[k] = __floats2half2_rn(0.5f * W2[2 * k], 0.5f * W2[2 * k + 1]);
    const float bias2 = 0.5f * b2[0];
    const __half2 binit = __halves2half2(__float2half_rn(bias2),
                                         __ushort_as_half((unsigned short)0));
    const __half2 hzero = __float2half2_rn(0.0f);

    // ============ Grid barrier (all 1024 blocks resident, 1 wave) =======
    __syncthreads();   // all prep STGs issued; all sWa/sWc reads done
    if (t == 0) {
        unsigned my_gen = *(volatile unsigned*)&g_gen;  // read BEFORE arriving
        __threadfence();                                 // release g_A/g_C writes
        unsigned old = atomicAdd(&g_count, 1);
        if (old == NBLOCKS - 1) {
            g_count = 0;                                 // reset for next replay
            __threadfence();
            atomicAdd(&g_gen, 1);                        // release everyone
        } else {
            unsigned g;
            do {
                __nanosleep(32);
                asm volatile("ld.acquire.gpu.u32 %0, [%1];"
                             : "=r"(g) : "l"(&g_gen) : "memory");
            } while (g == my_gen);
        }
    }
    __syncthreads();

    // ============ Phase B: pairwise tanh + dot + sigmoid ================
    const int b  = blockIdx.z;
    const int j  = blockIdx.x * JT + t;
    const int i0 = blockIdx.y * I_CHUNK;

    // C tile (I_CHUNK rows x 16 half2 = 2 KB): 128 float4, one per thread.
    reinterpret_cast<float4*>(sC)[t] =
        __ldcg(reinterpret_cast<const float4*>(g_C + ((size_t)b * NN + i0) * 16) + t);

    // Per-thread A' row (register-resident).
    float4 av[4];
    const float4* gA = reinterpret_cast<const float4*>(g_A + ((size_t)b * NN + j) * 16);
    #pragma unroll
    for (int q = 0; q < 4; q++) av[q] = __ldcg(gA + q);
    const __half2* Aj = reinterpret_cast<const __half2*>(av);

    __syncthreads();

    float* outp = out + (size_t)b * NN * NN + (size_t)i0 * NN + j;

    #pragma unroll 4
    for (int ii = 0; ii < I_CHUNK; ii += 2) {
        const float4* crow0 = reinterpret_cast<const float4*>(sC + ii * 16);
        const float4* crow1 = reinterpret_cast<const float4*>(sC + (ii + 1) * 16);

        // Two independent accumulation chains (i and i+1).
        __half2 a0 = binit, a1 = hzero, a2 = hzero, a3 = hzero;   // i
        __half2 b0 = binit, b1v = hzero, b2v = hzero, b3 = hzero; // i+1

        #pragma unroll
        for (int q = 0; q < 4; q++) {
            float4 cv0 = crow0[q];                      // broadcast LDS.128
            float4 cv1 = crow1[q];
            const __half2* c0 = reinterpret_cast<const __half2*>(&cv0);
            const __half2* c1 = reinterpret_cast<const __half2*>(&cv1);

            __half2 t00 = tanh2_approx(__hadd2(Aj[4 * q + 0], c0[0]));
            __half2 t10 = tanh2_approx(__hadd2(Aj[4 * q + 0], c1[0]));
            __half2 t01 = tanh2_approx(__hadd2(Aj[4 * q + 1], c0[1]));
            __half2 t11 = tanh2_approx(__hadd2(Aj[4 * q + 1], c1[1]));
            __half2 t02 = tanh2_approx(__hadd2(Aj[4 * q + 2], c0[2]));
            __half2 t12 = tanh2_approx(__hadd2(Aj[4 * q + 2], c1[2]));
            __half2 t03 = tanh2_approx(__hadd2(Aj[4 * q + 3], c0[3]));
            __half2 t13 = tanh2_approx(__hadd2(Aj[4 * q + 3], c1[3]));

            a0  = __hfma2(t00, w2h[4 * q + 0], a0);
            b0  = __hfma2(t10, w2h[4 * q + 0], b0);
            a1  = __hfma2(t01, w2h[4 * q + 1], a1);
            b1v = __hfma2(t11, w2h[4 * q + 1], b1v);
            a2  = __hfma2(t02, w2h[4 * q + 2], a2);
            b2v = __hfma2(t12, w2h[4 * q + 2], b2v);
            a3  = __hfma2(t03, w2h[4 * q + 3], a3);
            b3  = __hfma2(t13, w2h[4 * q + 3], b3);
        }

        // Lean epilogue per i: 3 HADD2 + 1 HADD + 1 cvt + MUFU + FFMA + STG.
        __half2 sa = __hadd2(__hadd2(a0, a1), __hadd2(a2, a3));
        __half2 sb = __hadd2(__hadd2(b0, b1v), __hadd2(b2v, b3));
        float hla = __half2float(__hadd(__low2half(sa), __high2half(sa)));
        float hlb = __half2float(__hadd(__low2half(sb), __high2half(sb)));

        outp[(size_t)ii * NN]       = fmaf(0.5f, tanhf_approx(hla), 0.5f);
        outp[(size_t)(ii + 1) * NN] = fmaf(0.5f, tanhf_approx(hlb), 0.5f);
    }
}

// ---------------------------------------------------------------------------
// Launch: ONE graph-capturable kernel, no allocations, no syncs.
// Inputs (metadata order): X, W1, b1, W2, b2. Output: float32 [4,1024,1024].
// ---------------------------------------------------------------------------
extern "C" void kernel_launch(void* const* d_in, const int* in_sizes, int n_in,
                              void* d_out, int out_size)
{
    const float* X  = (const float*)d_in[0];
    const float* W1 = (const float*)d_in[1];
    const float* b1 = (const float*)d_in[2];
    const float* W2 = (const float*)d_in[3];
    const float* b2 = (const float*)d_in[4];
    float* out = (float*)d_out;

    dim3 grid(NN / JT, NN / I_CHUNK, BB);   // (8, 32, 4) = 1024 blocks, 1 wave
    fused_kernel<<<grid, JT>>>(X, W1, b1, W2, b2, out);
}